// round 16
// baseline (speedup 1.0000x reference)
#include <cuda_runtime.h>
#include <cuda_fp16.h>
#include <cstdint>

// ----------------------------------------------------------------------------
// GIN forward on GB300 (base sm_103 PTX): CSR gather fused INTO the GEMM
// kernel with PING-PONG feature buffers (gather reads buf X, epilogue writes
// buf Y -> no intra-launch race). fp16 mma.sync 2-term exact-product GEMMs,
// power-of-2 dynamic-range scaling, fused pool+head.
// ----------------------------------------------------------------------------

#define NMAX 50048
#define EMAX 800000
#define HDIM 128
#define GMAX 512

#define H_SCALE_INV 0.0625f      // 1/16 : h storage scale
#define H_SCALE 16.0f
#define A_SCALE 256.0f           // GEMM input scale (fused layers)
#define A_SCALE_INV 0.00390625f  // 1/256

__device__ __half g_hA[(size_t)NMAX * HDIM];    // h/16 ping
__device__ __half g_hB[(size_t)NMAX * HDIM];    // h/16 pong (also layer0 mlp1 out)
__device__ int   g_deg[NMAX];
__device__ int   g_off[NMAX];
__device__ int   g_cnt[NMAX];
__device__ int   g_csr[EMAX];
// 9 weight mats x (hi plane 16384 + lo plane 16384) fp16, transposed [n][k]
__device__ __half g_wprep[9 * 32768];

// ------------------------------ helpers -------------------------------------

__device__ __forceinline__ uint32_t smem_to_u32(const void* p) {
    uint32_t a;
    asm("{ .reg .u64 t; cvta.to.shared.u64 t, %1; cvt.u32.u64 %0, t; }"
        : "=r"(a) : "l"(p));
    return a;
}

__device__ __forceinline__ void ldsm_x4(uint32_t r[4], uint32_t addr) {
    asm volatile("ldmatrix.sync.aligned.m8n8.x4.shared.b16 {%0,%1,%2,%3}, [%4];"
                 : "=r"(r[0]), "=r"(r[1]), "=r"(r[2]), "=r"(r[3]) : "r"(addr));
}

__device__ __forceinline__ void mma_f16(float c[4], const uint32_t a[4],
                                        const uint32_t b[2]) {
    asm volatile(
        "mma.sync.aligned.m16n8k16.row.col.f32.f16.f16.f32 "
        "{%0,%1,%2,%3}, {%4,%5,%6,%7}, {%8,%9}, {%0,%1,%2,%3};"
        : "+f"(c[0]), "+f"(c[1]), "+f"(c[2]), "+f"(c[3])
        : "r"(a[0]), "r"(a[1]), "r"(a[2]), "r"(a[3]), "r"(b[0]), "r"(b[1]));
}

__device__ __forceinline__ void cp16(uint32_t dst, const void* src) {
    asm volatile("cp.async.cg.shared.global [%0], [%1], 16;"
                 :: "r"(dst), "l"(src) : "memory");
}
#define CP_COMMIT() asm volatile("cp.async.commit_group;" ::: "memory")
#define CP_WAIT0()  asm volatile("cp.async.wait_group 0;" ::: "memory")
#define CP_WAIT1()  asm volatile("cp.async.wait_group 1;" ::: "memory")

__device__ __forceinline__ float4 h4_to_f4(uint2 r) {
    __half2 p0 = *reinterpret_cast<__half2*>(&r.x);
    __half2 p1 = *reinterpret_cast<__half2*>(&r.y);
    float2 f0 = __half22float2(p0);
    float2 f1 = __half22float2(p1);
    return make_float4(f0.x, f0.y, f1.x, f1.y);
}

__device__ __forceinline__ uint2 f4_to_h4(float4 v) {
    __half2 p0 = __floats2half2_rn(v.x, v.y);
    __half2 p1 = __floats2half2_rn(v.z, v.w);
    uint2 r;
    r.x = *reinterpret_cast<uint32_t*>(&p0);
    r.y = *reinterpret_cast<uint32_t*>(&p1);
    return r;
}

// ------------- Weight prep (fp16 hi/lo, [n][k]) + counter zeroing -----------

__global__ void wprep_kernel(const float* __restrict__ c1W2,
                             const float* __restrict__ cW1,
                             const float* __restrict__ cW2, int nl, int n) {
    int i = blockIdx.x * blockDim.x + threadIdx.x;
    if (i < n) { g_deg[i] = 0; g_cnt[i] = 0; }
    int total = (1 + 2 * nl) * 16384;
    if (i >= total) return;
    int m = i >> 14;
    int r = i & 16383;
    int k = r >> 7;
    int nn = r & 127;
    const float* src;
    if (m == 0) src = c1W2;
    else if (m <= nl) src = cW1 + (size_t)(m - 1) * 16384;
    else src = cW2 + (size_t)(m - 1 - nl) * 16384;
    float v = src[r];                 // [k][nn]
    __half hb = __float2half_rn(v);
    __half lb = __float2half_rn(v - __half2float(hb));
    int base = m * 32768;
    g_wprep[base + nn * 128 + k] = hb;
    g_wprep[base + 16384 + nn * 128 + k] = lb;
}

// --------------------------- CSR construction -------------------------------

__global__ void hist_kernel(const int* __restrict__ dst, int e, int n) {
    int i = blockIdx.x * blockDim.x + threadIdx.x;
    if (i < e) {
        int d = dst[i];
        if (d >= 0 && d < n) atomicAdd(&g_deg[d], 1);
    }
}

__global__ void scan_kernel(int n) {
    __shared__ int sums[1024];
    int t = threadIdx.x;
    int chunk = (n + 1023) >> 10;
    int start = t * chunk;
    int end = start + chunk; if (end > n) end = n;
    int s = 0;
    for (int i = start; i < end; i++) s += g_deg[i];
    sums[t] = s;
    __syncthreads();
    for (int d = 1; d < 1024; d <<= 1) {
        int v = (t >= d) ? sums[t - d] : 0;
        __syncthreads();
        sums[t] += v;
        __syncthreads();
    }
    int run = (t == 0) ? 0 : sums[t - 1];
    for (int i = start; i < end; i++) { g_off[i] = run; run += g_deg[i]; }
}

__global__ void fill_kernel(const int* __restrict__ src,
                            const int* __restrict__ dst, int e, int n) {
    int i = blockIdx.x * blockDim.x + threadIdx.x;
    if (i < e) {
        int d = dst[i];
        int s = src[i];
        if (d >= 0 && d < n && s >= 0 && s < n) {
            int p = g_off[d] + atomicAdd(&g_cnt[d], 1);
            g_csr[p] = s;
        }
    }
}

// -------------- Layer 0: fused agg(dim2) + MLP1 (warp per node) -------------

__global__ void agg_mlp0_kernel(const float* __restrict__ x,
                                const float* __restrict__ W1,
                                const float* __restrict__ b1, int n) {
    int gt = blockIdx.x * blockDim.x + threadIdx.x;
    int node = gt >> 5, lane = gt & 31;
    if (node >= n) return;
    int o = g_off[node], d = g_deg[node];
    float a0 = 0.0f, a1 = 0.0f;
    for (int e = lane; e < d; e += 32) {
        int s = g_csr[o + e];
        float2 v = *(const float2*)&x[s * 2];
        a0 += v.x; a1 += v.y;
    }
#pragma unroll
    for (int m = 16; m > 0; m >>= 1) {
        a0 += __shfl_xor_sync(0xFFFFFFFFu, a0, m);
        a1 += __shfl_xor_sync(0xFFFFFFFFu, a1, m);
    }
    float2 self = *(const float2*)&x[node * 2];
    a0 += self.x; a1 += self.y;

    int c = lane * 4;
    float4 w0 = *(const float4*)&W1[c];
    float4 w1 = *(const float4*)&W1[HDIM + c];
    float4 bb = *(const float4*)&b1[c];
    float4 v;
    v.x = fmaxf(fmaf(a0, w0.x, fmaf(a1, w1.x, bb.x)), 0.0f);
    v.y = fmaxf(fmaf(a0, w0.y, fmaf(a1, w1.y, bb.y)), 0.0f);
    v.z = fmaxf(fmaf(a0, w0.z, fmaf(a1, w1.z, bb.z)), 0.0f);
    v.w = fmaxf(fmaf(a0, w0.w, fmaf(a1, w1.w, bb.w)), 0.0f);
    *(uint2*)&g_hB[(size_t)node * HDIM + c] = f4_to_h4(v);
}

// ---------------- Fused gather + MLP GEMM (and single-GEMM mode) ------------
// Ag != nullptr => gather mode: CTA gathers its 128 rows from Ag (h/16) via
//                  CSR into the smem A plane (hpre/256). C MUST != Ag.
// Ag == nullptr => A loaded by cp.async from Aa (layer 0).
#define PITCH 272
#define PLANE 34816
#define A_OFF 2048
#define WA_OFF 36864
#define WB_OFF 106496
#define GEMM_SMEM_BYTES 176128

__device__ __forceinline__ void mma_block(uint32_t a0, uint32_t a1, uint32_t bw,
                                          float acc[2][8][4]) {
#pragma unroll
    for (int ks = 0; ks < 8; ks++) {
        uint32_t ko = ks * 32;
        uint32_t a[2][4];
        ldsm_x4(a[0], a0 + ko);
        ldsm_x4(a[1], a1 + ko);
        uint32_t bh[8][2], bl[8][2];
#pragma unroll
        for (int q = 0; q < 4; q++) {
            ldsm_x4(&bh[2 * q][0], bw + q * 16 * PITCH + ko);
            ldsm_x4(&bl[2 * q][0], bw + PLANE + q * 16 * PITCH + ko);
        }
#pragma unroll
        for (int ti = 0; ti < 2; ti++) {
#pragma unroll
            for (int tj = 0; tj < 8; tj++) {
                mma_f16(acc[ti][tj], a[ti], bh[tj]);
                mma_f16(acc[ti][tj], a[ti], bl[tj]);
            }
        }
    }
}

__global__ void __launch_bounds__(256)
gemm_mlp(const __half* __restrict__ Aa,     // cp.async A source (layer 0)
         const __half* __restrict__ Ag,     // gather source (fused layers)
         const __half* __restrict__ W1p,    // nullptr => single GEMM
         const __half* __restrict__ W2p,
         const float* __restrict__ b1, const float* __restrict__ b2,
         const float* __restrict__ gamma, const float* __restrict__ beta,
         const float* __restrict__ mean, const float* __restrict__ var,
         __half* __restrict__ C, int n, float ascale) {
    extern __shared__ __align__(16) char smem[];
    uint32_t sb = smem_to_u32(smem);
    int tid = threadIdx.x;
    int wid = tid >> 5;
    int lane = tid & 31;
    int row0 = blockIdx.x * 128;
    bool fused = (W1p != nullptr);
    bool gather = (Ag != nullptr);

    if (!gather) {
#pragma unroll
        for (int it = 0; it < 8; it++) {
            int idx = it * 256 + tid;            // 0..2047
            int row = idx >> 4, cu = idx & 15;
            cp16(sb + A_OFF + row * PITCH + cu * 16,
                 Aa + ((size_t)(row0 + row) * 128 + cu * 8));
        }
    }
    const __half* Wa = fused ? W1p : W2p;
#pragma unroll
    for (int it = 0; it < 16; it++) {
        int idx = it * 256 + tid;            // 0..4095
        int plane = idx >> 11;
        int r2 = idx & 2047;
        int row = r2 >> 4, cu = r2 & 15;
        cp16(sb + WA_OFF + plane * PLANE + row * PITCH + cu * 16,
             Wa + plane * 16384 + row * 128 + cu * 8);
    }
    CP_COMMIT();
    if (fused) {
#pragma unroll
        for (int it = 0; it < 16; it++) {
            int idx = it * 256 + tid;
            int plane = idx >> 11;
            int r2 = idx & 2047;
            int row = r2 >> 4, cu = r2 & 15;
            cp16(sb + WB_OFF + plane * PLANE + row * PITCH + cu * 16,
                 W2p + plane * 16384 + row * 128 + cu * 8);
        }
        CP_COMMIT();
    }

    if (gather) {
        // warp w gathers rows [w*16, w*16+16): acc = (h + sum nbr h)/16 -> /256
        const uint2* hp = (const uint2*)Ag;
        for (int rr = 0; rr < 16; rr++) {
            int row = (wid << 4) + rr;
            int node = row0 + row;
            float4 acc = make_float4(0.f, 0.f, 0.f, 0.f);
            if (node < n) {
                acc = h4_to_f4(hp[(size_t)node * 32 + lane]);
                int o = g_off[node], d = g_deg[node];
                int e = 0;
                int d4 = d & ~3;
                for (; e < d4; e += 4) {
                    int s0 = g_csr[o + e];
                    int s1 = g_csr[o + e + 1];
                    int s2 = g_csr[o + e + 2];
                    int s3 = g_csr[o + e + 3];
                    float4 v0 = h4_to_f4(hp[(size_t)s0 * 32 + lane]);
                    float4 v1 = h4_to_f4(hp[(size_t)s1 * 32 + lane]);
                    float4 v2 = h4_to_f4(hp[(size_t)s2 * 32 + lane]);
                    float4 v3 = h4_to_f4(hp[(size_t)s3 * 32 + lane]);
                    acc.x += v0.x + v1.x + v2.x + v3.x;
                    acc.y += v0.y + v1.y + v2.y + v3.y;
                    acc.z += v0.z + v1.z + v2.z + v3.z;
                    acc.w += v0.w + v1.w + v2.w + v3.w;
                }
                for (; e < d; e++) {
                    int s = g_csr[o + e];
                    float4 v = h4_to_f4(hp[(size_t)s * 32 + lane]);
                    acc.x += v.x; acc.y += v.y; acc.z += v.z; acc.w += v.w;
                }
                acc.x *= H_SCALE_INV; acc.y *= H_SCALE_INV;
                acc.z *= H_SCALE_INV; acc.w *= H_SCALE_INV;
            }
            *(uint2*)(smem + A_OFF + row * PITCH + lane * 8) = f4_to_h4(acc);
        }
    }

    float* sm_b1 = (float*)(smem + 0);     // b1 / ascale
    float* sm_b2 = (float*)(smem + 512);
    float* sm_sc = (float*)(smem + 1024);  // BN scale * 1/16
    float* sm_sh = (float*)(smem + 1536);
    if (tid < 128) {
        sm_b1[tid] = fused ? b1[tid] * A_SCALE_INV : 0.0f;
        sm_b2[tid] = b2[tid];
        float scv = 1.0f, shv = 0.0f;
        if (gamma != nullptr) {
            scv = gamma[tid] * rsqrtf(var[tid] + 1e-5f);
            shv = beta[tid] - mean[tid] * scv;
        }
        sm_sc[tid] = scv * H_SCALE_INV;
        sm_sh[tid] = shv * H_SCALE_INV;
    }
    if (fused) { CP_WAIT1(); } else { CP_WAIT0(); }
    __syncthreads();

    int m0 = (wid & 3) * 32;
    int n0 = (wid >> 2) * 64;
    int lr = lane & 7;
    int mi = lane >> 3;
    uint32_t a0_addr = sb + A_OFF + (uint32_t)(m0 + (mi & 1) * 8 + lr) * PITCH + (mi >> 1) * 16;
    uint32_t a1_addr = a0_addr + 16 * PITCH;
    uint32_t ba_addr = sb + WA_OFF + (uint32_t)(n0 + (mi >> 1) * 8 + lr) * PITCH + (mi & 1) * 16;

    float acc[2][8][4];
#pragma unroll
    for (int ti = 0; ti < 2; ti++)
#pragma unroll
        for (int tj = 0; tj < 8; tj++)
#pragma unroll
            for (int q = 0; q < 4; q++) acc[ti][tj][q] = 0.0f;

    mma_block(a0_addr, a1_addr, ba_addr, acc);

    int rb = m0 + (lane >> 2);
    int cb = n0 + (lane & 3) * 2;

    if (fused) {
        __syncthreads();
        CP_WAIT0();
        // h1/256 = relu(acc + b1/256) -> fp16 A plane
#pragma unroll
        for (int tj = 0; tj < 8; tj++) {
            int col = cb + tj * 8;
            float bb0 = sm_b1[col], bb1 = sm_b1[col + 1];
#pragma unroll
            for (int ti = 0; ti < 2; ti++) {
                int r = rb + ti * 16;
                __half2 p0 = __floats2half2_rn(fmaxf(acc[ti][tj][0] + bb0, 0.0f),
                                               fmaxf(acc[ti][tj][1] + bb1, 0.0f));
                *(uint32_t*)(smem + A_OFF + r * PITCH + col * 2) =
                    *reinterpret_cast<uint32_t*>(&p0);
                __half2 p1 = __floats2half2_rn(fmaxf(acc[ti][tj][2] + bb0, 0.0f),
                                               fmaxf(acc[ti][tj][3] + bb1, 0.0f));
                *(uint32_t*)(smem + A_OFF + (r + 8) * PITCH + col * 2) =
                    *reinterpret_cast<uint32_t*>(&p1);
                acc[ti][tj][0] = 0.0f; acc[ti][tj][1] = 0.0f;
                acc[ti][tj][2] = 0.0f; acc[ti][tj][3] = 0.0f;
            }
        }
        __syncthreads();
        uint32_t bb_addr = sb + WB_OFF + (uint32_t)(n0 + (mi >> 1) * 8 + lr) * PITCH + (mi & 1) * 16;
        mma_block(a0_addr, a1_addr, bb_addr, acc);
    }

    // final epilogue: h/16 = (relu(acc*ascale + b2)*sc + sh)/16 -> C (fp16)
    int rbase = row0 + rb;
#pragma unroll
    for (int tj = 0; tj < 8; tj++) {
        int col = cb + tj * 8;
        float b0 = sm_b2[col], b1v = sm_b2[col + 1];
        float s0 = sm_sc[col], s1 = sm_sc[col + 1];
        float h0 = sm_sh[col], h1 = sm_sh[col + 1];
#pragma unroll
        for (int ti = 0; ti < 2; ti++) {
            int r = rbase + ti * 16;
            if (r < n) {
                float vx = fmaxf(fmaf(acc[ti][tj][0], ascale, b0), 0.0f) * s0 + h0;
                float vy = fmaxf(fmaf(acc[ti][tj][1], ascale, b1v), 0.0f) * s1 + h1;
                *(__half2*)&C[(size_t)r * 128 + col] = __floats2half2_rn(vx, vy);
            }
            if (r + 8 < n) {
                float vx = fmaxf(fmaf(acc[ti][tj][2], ascale, b0), 0.0f) * s0 + h0;
                float vy = fmaxf(fmaf(acc[ti][tj][3], ascale, b1v), 0.0f) * s1 + h1;
                *(__half2*)&C[(size_t)(r + 8) * 128 + col] = __floats2half2_rn(vx, vy);
            }
        }
    }
}

// --------------------------- Fused pool + head ------------------------------

__global__ void pool_head_kernel(const int* __restrict__ batch, int n,
                                 const __half* __restrict__ hfin,
                                 const float* __restrict__ lin1W,
                                 const float* __restrict__ lin1b,
                                 const float* __restrict__ lin2W,
                                 const float* __restrict__ lin2b,
                                 float* __restrict__ out) {
    int gid = blockIdx.x;
    int j = threadIdx.x;
    __shared__ int se[2];
    __shared__ float row[128];
    __shared__ float red[128];
    if (j < 2) {
        int target = gid + j;
        int lo = 0, hi = n;
        while (lo < hi) {
            int mid = (lo + hi) >> 1;
            if (batch[mid] < target) lo = mid + 1; else hi = mid;
        }
        se[j] = lo;
    }
    __syncthreads();
    float acc = 0.0f;
    int s = se[0], e = se[1];
    for (int r = s; r < e; r++) acc += __half2float(hfin[(size_t)r * HDIM + j]);
    row[j] = acc * H_SCALE;
    __syncthreads();
    float a = lin1b[j];
#pragma unroll 8
    for (int k = 0; k < 128; k++) a = fmaf(row[k], lin1W[k * 128 + j], a);
    a = fmaxf(a, 0.0f);
    red[j] = a * lin2W[j];
    __syncthreads();
#pragma unroll
    for (int st = 64; st > 0; st >>= 1) {
        if (j < st) red[j] += red[j + st];
        __syncthreads();
    }
    if (j == 0) out[gid] = red[0] + lin2b[0];
}

// ------------------------------- Launch --------------------------------------

extern "C" void kernel_launch(void* const* d_in, const int* in_sizes, int n_in,
                              void* d_out, int out_size) {
    const float* x     = (const float*)d_in[0];
    const int*   ei    = (const int*)d_in[1];
    const int*   batch = (const int*)d_in[2];
    const float* c1W1 = (const float*)d_in[3];
    const float* c1b1 = (const float*)d_in[4];
    const float* c1W2 = (const float*)d_in[5];
    const float* c1b2 = (const float*)d_in[6];
    const float* c1gm = (const float*)d_in[7];
    const float* c1bt = (const float*)d_in[8];
    const float* c1mn = (const float*)d_in[9];
    const float* c1vr = (const float*)d_in[10];
    const float* cW1  = (const float*)d_in[11];
    const float* cb1  = (const float*)d_in[12];
    const float* cW2  = (const float*)d_in[13];
    const float* cb2  = (const float*)d_in[14];
    const float* cgm  = (const float*)d_in[15];
    const float* cbt  = (const float*)d_in[16];
    const float* cmn  = (const float*)d_in[17];
    const float* cvr  = (const float*)d_in[18];
    const float* l1W  = (const float*)d_in[19];
    const float* l1b  = (const float*)d_in[20];
    const float* l2W  = (const float*)d_in[21];
    const float* l2b  = (const float*)d_in[22];
    float* out = (float*)d_out;

    int n = in_sizes[0] / 2;
    int e = in_sizes[1] / 2;
    int nl = in_sizes[11] / (HDIM * HDIM);
    int g = out_size;

    const int* src = ei;
    const int* dst = ei + e;

    __half *p_hA, *p_hB, *p_wprep;
    cudaGetSymbolAddress((void**)&p_hA, g_hA);
    cudaGetSymbolAddress((void**)&p_hB, g_hB);
    cudaGetSymbolAddress((void**)&p_wprep, g_wprep);

    cudaFuncSetAttribute(gemm_mlp, cudaFuncAttributeMaxDynamicSharedMemorySize,
                         GEMM_SMEM_BYTES);

    // launches: 0 wprep(+zero), 1 hist, 2 scan, 3 fill, 4 agg_mlp0,
    //           5 gemm0 (profiled), 6..9 fused gemms, 10 pool_head
    int wtot = (1 + 2 * nl) * 16384;
    wprep_kernel<<<(wtot + 255) / 256, 256>>>(c1W2, cW1, cW2, nl, n);
    hist_kernel<<<(e + 255) / 256, 256>>>(dst, e, n);
    scan_kernel<<<1, 1024>>>(n);
    fill_kernel<<<(e + 255) / 256, 256>>>(src, dst, e, n);

    int gemm_blocks = (n + 127) / 128;
    int warp_grid = (n * 32 + 255) / 256;

    // Layer 0: agg(dim2)+MLP1 -> g_hB; gemm0: A=g_hB (cp.async) -> h into g_hA
    agg_mlp0_kernel<<<warp_grid, 256>>>(x, c1W1, c1b1, n);
    gemm_mlp<<<gemm_blocks, 256, GEMM_SMEM_BYTES>>>(
        p_hB, nullptr, nullptr, p_wprep, nullptr, c1b2,
        c1gm, c1bt, c1mn, c1vr, p_hA, n, 1.0f);

    // Layers 1..nl: ping-pong (gather cur -> write nxt)
    __half* cur = p_hA;
    __half* nxt = p_hB;
    for (int i = 0; i < nl; i++) {
        gemm_mlp<<<gemm_blocks, 256, GEMM_SMEM_BYTES>>>(
            nullptr, cur,
            p_wprep + (size_t)(1 + i) * 32768,
            p_wprep + (size_t)(1 + nl + i) * 32768,
            cb1 + (size_t)i * HDIM, cb2 + (size_t)i * HDIM,
            cgm + (size_t)i * HDIM, cbt + (size_t)i * HDIM,
            cmn + (size_t)i * HDIM, cvr + (size_t)i * HDIM, nxt, n, A_SCALE);
        __half* t = cur; cur = nxt; nxt = t;
    }

    // Fused pool + head on final buffer (cur)
    pool_head_kernel<<<g, 128>>>(batch, n, cur, l1W, l1b, l2W, l2b, out);
}

// round 17
// speedup vs baseline: 1.6310x; 1.6310x over previous
#include <cuda_runtime.h>
#include <cuda_fp16.h>
#include <cstdint>

// ----------------------------------------------------------------------------
// GIN forward on GB300 (base sm_103 PTX): high-occupancy CSR gather kernel
// (fp16 features) + fused-MLP mma.sync fp16 GEMM with W-plane reuse
// (3 smem planes -> 2 CTAs/SM), power-of-2 dynamic-range scaling, fused
// pool+head. g_h stores h/16; g_hpre stores hpre/256.
// ----------------------------------------------------------------------------

#define NMAX 50048
#define EMAX 800000
#define HDIM 128
#define GMAX 512

#define H_SCALE_INV 0.0625f      // 1/16 : h storage scale
#define H_SCALE 16.0f
#define A_SCALE 256.0f           // GEMM input scale (fused layers)
#define A_SCALE_INV 0.00390625f  // 1/256

__device__ __half g_h[(size_t)NMAX * HDIM];     // h/16 (fp16)
__device__ __half g_hpre[(size_t)NMAX * HDIM];  // hpre/256 (fp16)
__device__ __half g_h1[(size_t)NMAX * HDIM];    // layer0 mlp1 out (unscaled)
__device__ int   g_deg[NMAX];
__device__ int   g_off[NMAX];
__device__ int   g_cnt[NMAX];
__device__ int   g_csr[EMAX];
// 9 weight mats x (hi plane 16384 + lo plane 16384) fp16, transposed [n][k]
__device__ __half g_wprep[9 * 32768];

// ------------------------------ helpers -------------------------------------

__device__ __forceinline__ uint32_t smem_to_u32(const void* p) {
    uint32_t a;
    asm("{ .reg .u64 t; cvta.to.shared.u64 t, %1; cvt.u32.u64 %0, t; }"
        : "=r"(a) : "l"(p));
    return a;
}

__device__ __forceinline__ void ldsm_x4(uint32_t r[4], uint32_t addr) {
    asm volatile("ldmatrix.sync.aligned.m8n8.x4.shared.b16 {%0,%1,%2,%3}, [%4];"
                 : "=r"(r[0]), "=r"(r[1]), "=r"(r[2]), "=r"(r[3]) : "r"(addr));
}

__device__ __forceinline__ void mma_f16(float c[4], const uint32_t a[4],
                                        const uint32_t b[2]) {
    asm volatile(
        "mma.sync.aligned.m16n8k16.row.col.f32.f16.f16.f32 "
        "{%0,%1,%2,%3}, {%4,%5,%6,%7}, {%8,%9}, {%0,%1,%2,%3};"
        : "+f"(c[0]), "+f"(c[1]), "+f"(c[2]), "+f"(c[3])
        : "r"(a[0]), "r"(a[1]), "r"(a[2]), "r"(a[3]), "r"(b[0]), "r"(b[1]));
}

__device__ __forceinline__ void cp16(uint32_t dst, const void* src) {
    asm volatile("cp.async.cg.shared.global [%0], [%1], 16;"
                 :: "r"(dst), "l"(src) : "memory");
}
#define CP_COMMIT() asm volatile("cp.async.commit_group;" ::: "memory")
#define CP_WAIT0()  asm volatile("cp.async.wait_group 0;" ::: "memory")

__device__ __forceinline__ float4 h4_to_f4(uint2 r) {
    __half2 p0 = *reinterpret_cast<__half2*>(&r.x);
    __half2 p1 = *reinterpret_cast<__half2*>(&r.y);
    float2 f0 = __half22float2(p0);
    float2 f1 = __half22float2(p1);
    return make_float4(f0.x, f0.y, f1.x, f1.y);
}

__device__ __forceinline__ uint2 f4_to_h4(float4 v) {
    __half2 p0 = __floats2half2_rn(v.x, v.y);
    __half2 p1 = __floats2half2_rn(v.z, v.w);
    uint2 r;
    r.x = *reinterpret_cast<uint32_t*>(&p0);
    r.y = *reinterpret_cast<uint32_t*>(&p1);
    return r;
}

// ------------- Weight prep (fp16 hi/lo, [n][k]) + counter zeroing -----------

__global__ void wprep_kernel(const float* __restrict__ c1W2,
                             const float* __restrict__ cW1,
                             const float* __restrict__ cW2, int nl, int n) {
    int i = blockIdx.x * blockDim.x + threadIdx.x;
    if (i < n) { g_deg[i] = 0; g_cnt[i] = 0; }
    int total = (1 + 2 * nl) * 16384;
    if (i >= total) return;
    int m = i >> 14;
    int r = i & 16383;
    int k = r >> 7;
    int nn = r & 127;
    const float* src;
    if (m == 0) src = c1W2;
    else if (m <= nl) src = cW1 + (size_t)(m - 1) * 16384;
    else src = cW2 + (size_t)(m - 1 - nl) * 16384;
    float v = src[r];                 // [k][nn]
    __half hb = __float2half_rn(v);
    __half lb = __float2half_rn(v - __half2float(hb));
    int base = m * 32768;
    g_wprep[base + nn * 128 + k] = hb;
    g_wprep[base + 16384 + nn * 128 + k] = lb;
}

// --------------------------- CSR construction -------------------------------

__global__ void hist_kernel(const int* __restrict__ dst, int e, int n) {
    int i = blockIdx.x * blockDim.x + threadIdx.x;
    if (i < e) {
        int d = dst[i];
        if (d >= 0 && d < n) atomicAdd(&g_deg[d], 1);
    }
}

__global__ void scan_kernel(int n) {
    __shared__ int sums[1024];
    int t = threadIdx.x;
    int chunk = (n + 1023) >> 10;
    int start = t * chunk;
    int end = start + chunk; if (end > n) end = n;
    int s = 0;
    for (int i = start; i < end; i++) s += g_deg[i];
    sums[t] = s;
    __syncthreads();
    for (int d = 1; d < 1024; d <<= 1) {
        int v = (t >= d) ? sums[t - d] : 0;
        __syncthreads();
        sums[t] += v;
        __syncthreads();
    }
    int run = (t == 0) ? 0 : sums[t - 1];
    for (int i = start; i < end; i++) { g_off[i] = run; run += g_deg[i]; }
}

__global__ void fill_kernel(const int* __restrict__ src,
                            const int* __restrict__ dst, int e, int n) {
    int i = blockIdx.x * blockDim.x + threadIdx.x;
    if (i < e) {
        int d = dst[i];
        int s = src[i];
        if (d >= 0 && d < n && s >= 0 && s < n) {
            int p = g_off[d] + atomicAdd(&g_cnt[d], 1);
            g_csr[p] = s;
        }
    }
}

// -------------- Layer 0: fused agg(dim2) + MLP1 (warp per node) -------------

__global__ void agg_mlp0_kernel(const float* __restrict__ x,
                                const float* __restrict__ W1,
                                const float* __restrict__ b1, int n) {
    int gt = blockIdx.x * blockDim.x + threadIdx.x;
    int node = gt >> 5, lane = gt & 31;
    if (node >= n) return;
    int o = g_off[node], d = g_deg[node];
    float a0 = 0.0f, a1 = 0.0f;
    for (int e = lane; e < d; e += 32) {
        int s = g_csr[o + e];
        float2 v = *(const float2*)&x[s * 2];
        a0 += v.x; a1 += v.y;
    }
#pragma unroll
    for (int m = 16; m > 0; m >>= 1) {
        a0 += __shfl_xor_sync(0xFFFFFFFFu, a0, m);
        a1 += __shfl_xor_sync(0xFFFFFFFFu, a1, m);
    }
    float2 self = *(const float2*)&x[node * 2];
    a0 += self.x; a1 += self.y;

    int c = lane * 4;
    float4 w0 = *(const float4*)&W1[c];
    float4 w1 = *(const float4*)&W1[HDIM + c];
    float4 bb = *(const float4*)&b1[c];
    float4 v;
    v.x = fmaxf(fmaf(a0, w0.x, fmaf(a1, w1.x, bb.x)), 0.0f);
    v.y = fmaxf(fmaf(a0, w0.y, fmaf(a1, w1.y, bb.y)), 0.0f);
    v.z = fmaxf(fmaf(a0, w0.z, fmaf(a1, w1.z, bb.z)), 0.0f);
    v.w = fmaxf(fmaf(a0, w0.w, fmaf(a1, w1.w, bb.w)), 0.0f);
    *(uint2*)&g_h1[(size_t)node * HDIM + c] = f4_to_h4(v);
}

// --------------------- Aggregation for 128-dim layers -----------------------
// High occupancy (no smem): warp per node; g_h (h/16) -> g_hpre (hpre/256).
__global__ void agg_kernel(int n) {
    int gt = blockIdx.x * blockDim.x + threadIdx.x;
    int node = gt >> 5, lane = gt & 31;
    if (node >= n) return;
    const uint2* hp = (const uint2*)g_h;
    float4 acc = h4_to_f4(hp[(size_t)node * 32 + lane]);
    int o = g_off[node], d = g_deg[node];
    int e = 0;
    int d4 = d & ~3;
    for (; e < d4; e += 4) {
        int s0 = g_csr[o + e];
        int s1 = g_csr[o + e + 1];
        int s2 = g_csr[o + e + 2];
        int s3 = g_csr[o + e + 3];
        float4 v0 = h4_to_f4(hp[(size_t)s0 * 32 + lane]);
        float4 v1 = h4_to_f4(hp[(size_t)s1 * 32 + lane]);
        float4 v2 = h4_to_f4(hp[(size_t)s2 * 32 + lane]);
        float4 v3 = h4_to_f4(hp[(size_t)s3 * 32 + lane]);
        acc.x += v0.x + v1.x + v2.x + v3.x;
        acc.y += v0.y + v1.y + v2.y + v3.y;
        acc.z += v0.z + v1.z + v2.z + v3.z;
        acc.w += v0.w + v1.w + v2.w + v3.w;
    }
    for (; e < d; e++) {
        int s = g_csr[o + e];
        float4 v = h4_to_f4(hp[(size_t)s * 32 + lane]);
        acc.x += v.x; acc.y += v.y; acc.z += v.z; acc.w += v.w;
    }
    acc.x *= H_SCALE_INV; acc.y *= H_SCALE_INV;
    acc.z *= H_SCALE_INV; acc.w *= H_SCALE_INV;
    *(uint2*)&g_hpre[(size_t)node * HDIM + lane * 4] = f4_to_h4(acc);
}

// ------------------- Fused MLP GEMM with W-plane reuse -----------------------
// smem: params 2048 | A plane 34816 | W hi 34816 | W lo 34816 = 106496 bytes
// -> 2 CTAs/SM. W1 staged first; after gemm1 the SAME planes are refilled
// with W2 (cp.async) while acc is converted into the A plane.
#define PITCH 272
#define PLANE 34816
#define A_OFF 2048
#define W_OFF 36864
#define GEMM_SMEM_BYTES 106496

__device__ __forceinline__ void mma_block(uint32_t a0, uint32_t a1, uint32_t bw,
                                          float acc[2][8][4]) {
#pragma unroll
    for (int ks = 0; ks < 8; ks++) {
        uint32_t ko = ks * 32;
        uint32_t a[2][4];
        ldsm_x4(a[0], a0 + ko);
        ldsm_x4(a[1], a1 + ko);
        uint32_t bh[8][2], bl[8][2];
#pragma unroll
        for (int q = 0; q < 4; q++) {
            ldsm_x4(&bh[2 * q][0], bw + q * 16 * PITCH + ko);
            ldsm_x4(&bl[2 * q][0], bw + PLANE + q * 16 * PITCH + ko);
        }
#pragma unroll
        for (int ti = 0; ti < 2; ti++) {
#pragma unroll
            for (int tj = 0; tj < 8; tj++) {
                mma_f16(acc[ti][tj], a[ti], bh[tj]);
                mma_f16(acc[ti][tj], a[ti], bl[tj]);
            }
        }
    }
}

__global__ void __launch_bounds__(256, 2)
gemm_mlp(const __half* __restrict__ Aa,
         const __half* __restrict__ W1p,   // nullptr => single GEMM
         const __half* __restrict__ W2p,
         const float* __restrict__ b1, const float* __restrict__ b2,
         const float* __restrict__ gamma, const float* __restrict__ beta,
         const float* __restrict__ mean, const float* __restrict__ var,
         __half* __restrict__ C, int n, float ascale) {
    extern __shared__ __align__(16) char smem[];
    uint32_t sb = smem_to_u32(smem);
    int tid = threadIdx.x;
    int wid = tid >> 5;
    int lane = tid & 31;
    int row0 = blockIdx.x * 128;
    bool fused = (W1p != nullptr);

    // stage A + first W
#pragma unroll
    for (int it = 0; it < 8; it++) {
        int idx = it * 256 + tid;            // 0..2047
        int row = idx >> 4, cu = idx & 15;
        cp16(sb + A_OFF + row * PITCH + cu * 16,
             Aa + ((size_t)(row0 + row) * 128 + cu * 8));
    }
    const __half* Wa = fused ? W1p : W2p;
#pragma unroll
    for (int it = 0; it < 16; it++) {
        int idx = it * 256 + tid;            // 0..4095
        int plane = idx >> 11;
        int r2 = idx & 2047;
        int row = r2 >> 4, cu = r2 & 15;
        cp16(sb + W_OFF + plane * PLANE + row * PITCH + cu * 16,
             Wa + plane * 16384 + row * 128 + cu * 8);
    }
    CP_COMMIT();

    float* sm_b1 = (float*)(smem + 0);     // b1 / ascale
    float* sm_b2 = (float*)(smem + 512);
    float* sm_sc = (float*)(smem + 1024);  // BN scale * 1/16
    float* sm_sh = (float*)(smem + 1536);
    if (tid < 128) {
        sm_b1[tid] = fused ? b1[tid] * A_SCALE_INV : 0.0f;
        sm_b2[tid] = b2[tid];
        float scv = 1.0f, shv = 0.0f;
        if (gamma != nullptr) {
            scv = gamma[tid] * rsqrtf(var[tid] + 1e-5f);
            shv = beta[tid] - mean[tid] * scv;
        }
        sm_sc[tid] = scv * H_SCALE_INV;
        sm_sh[tid] = shv * H_SCALE_INV;
    }
    CP_WAIT0();
    __syncthreads();

    int m0 = (wid & 3) * 32;
    int n0 = (wid >> 2) * 64;
    int lr = lane & 7;
    int mi = lane >> 3;
    uint32_t a0_addr = sb + A_OFF + (uint32_t)(m0 + (mi & 1) * 8 + lr) * PITCH + (mi >> 1) * 16;
    uint32_t a1_addr = a0_addr + 16 * PITCH;
    uint32_t bw_addr = sb + W_OFF + (uint32_t)(n0 + (mi >> 1) * 8 + lr) * PITCH + (mi & 1) * 16;

    float acc[2][8][4];
#pragma unroll
    for (int ti = 0; ti < 2; ti++)
#pragma unroll
        for (int tj = 0; tj < 8; tj++)
#pragma unroll
            for (int q = 0; q < 4; q++) acc[ti][tj][q] = 0.0f;

    mma_block(a0_addr, a1_addr, bw_addr, acc);

    int rb = m0 + (lane >> 2);
    int cb = n0 + (lane & 3) * 2;

    if (fused) {
        __syncthreads();          // all warps done reading W1 + A planes
        // refill W planes with W2 (overlaps the acc->A conversion below)
#pragma unroll
        for (int it = 0; it < 16; it++) {
            int idx = it * 256 + tid;
            int plane = idx >> 11;
            int r2 = idx & 2047;
            int row = r2 >> 4, cu = r2 & 15;
            cp16(sb + W_OFF + plane * PLANE + row * PITCH + cu * 16,
                 W2p + plane * 16384 + row * 128 + cu * 8);
        }
        CP_COMMIT();
        // h1/256 = relu(acc + b1/256) -> fp16 into A plane
#pragma unroll
        for (int tj = 0; tj < 8; tj++) {
            int col = cb + tj * 8;
            float bb0 = sm_b1[col], bb1 = sm_b1[col + 1];
#pragma unroll
            for (int ti = 0; ti < 2; ti++) {
                int r = rb + ti * 16;
                __half2 p0 = __floats2half2_rn(fmaxf(acc[ti][tj][0] + bb0, 0.0f),
                                               fmaxf(acc[ti][tj][1] + bb1, 0.0f));
                *(uint32_t*)(smem + A_OFF + r * PITCH + col * 2) =
                    *reinterpret_cast<uint32_t*>(&p0);
                __half2 p1 = __floats2half2_rn(fmaxf(acc[ti][tj][2] + bb0, 0.0f),
                                               fmaxf(acc[ti][tj][3] + bb1, 0.0f));
                *(uint32_t*)(smem + A_OFF + (r + 8) * PITCH + col * 2) =
                    *reinterpret_cast<uint32_t*>(&p1);
                acc[ti][tj][0] = 0.0f; acc[ti][tj][1] = 0.0f;
                acc[ti][tj][2] = 0.0f; acc[ti][tj][3] = 0.0f;
            }
        }
        CP_WAIT0();
        __syncthreads();
        mma_block(a0_addr, a1_addr, bw_addr, acc);
    }

    // final epilogue: h/16 = (relu(acc*ascale + b2)*sc + sh)/16 -> C (fp16)
    int rbase = row0 + rb;
#pragma unroll
    for (int tj = 0; tj < 8; tj++) {
        int col = cb + tj * 8;
        float b0 = sm_b2[col], b1v = sm_b2[col + 1];
        float s0 = sm_sc[col], s1 = sm_sc[col + 1];
        float h0 = sm_sh[col], h1 = sm_sh[col + 1];
#pragma unroll
        for (int ti = 0; ti < 2; ti++) {
            int r = rbase + ti * 16;
            if (r < n) {
                float vx = fmaxf(fmaf(acc[ti][tj][0], ascale, b0), 0.0f) * s0 + h0;
                float vy = fmaxf(fmaf(acc[ti][tj][1], ascale, b1v), 0.0f) * s1 + h1;
                *(__half2*)&C[(size_t)r * 128 + col] = __floats2half2_rn(vx, vy);
            }
            if (r + 8 < n) {
                float vx = fmaxf(fmaf(acc[ti][tj][2], ascale, b0), 0.0f) * s0 + h0;
                float vy = fmaxf(fmaf(acc[ti][tj][3], ascale, b1v), 0.0f) * s1 + h1;
                *(__half2*)&C[(size_t)(r + 8) * 128 + col] = __floats2half2_rn(vx, vy);
            }
        }
    }
}

// --------------------------- Fused pool + head ------------------------------

__global__ void pool_head_kernel(const int* __restrict__ batch, int n,
                                 const float* __restrict__ lin1W,
                                 const float* __restrict__ lin1b,
                                 const float* __restrict__ lin2W,
                                 const float* __restrict__ lin2b,
                                 float* __restrict__ out) {
    int gid = blockIdx.x;
    int j = threadIdx.x;
    __shared__ int se[2];
    __shared__ float row[128];
    __shared__ float red[128];
    if (j < 2) {
        int target = gid + j;
        int lo = 0, hi = n;
        while (lo < hi) {
            int mid = (lo + hi) >> 1;
            if (batch[mid] < target) lo = mid + 1; else hi = mid;
        }
        se[j] = lo;
    }
    __syncthreads();
    float acc = 0.0f;
    int s = se[0], e = se[1];
    for (int r = s; r < e; r++) acc += __half2float(g_h[(size_t)r * HDIM + j]);
    row[j] = acc * H_SCALE;
    __syncthreads();
    float a = lin1b[j];
#pragma unroll 8
    for (int k = 0; k < 128; k++) a = fmaf(row[k], lin1W[k * 128 + j], a);
    a = fmaxf(a, 0.0f);
    red[j] = a * lin2W[j];
    __syncthreads();
#pragma unroll
    for (int st = 64; st > 0; st >>= 1) {
        if (j < st) red[j] += red[j + st];
        __syncthreads();
    }
    if (j == 0) out[gid] = red[0] + lin2b[0];
}

// ------------------------------- Launch --------------------------------------

extern "C" void kernel_launch(void* const* d_in, const int* in_sizes, int n_in,
                              void* d_out, int out_size) {
    const float* x     = (const float*)d_in[0];
    const int*   ei    = (const int*)d_in[1];
    const int*   batch = (const int*)d_in[2];
    const float* c1W1 = (const float*)d_in[3];
    const float* c1b1 = (const float*)d_in[4];
    const float* c1W2 = (const float*)d_in[5];
    const float* c1b2 = (const float*)d_in[6];
    const float* c1gm = (const float*)d_in[7];
    const float* c1bt = (const float*)d_in[8];
    const float* c1mn = (const float*)d_in[9];
    const float* c1vr = (const float*)d_in[10];
    const float* cW1  = (const float*)d_in[11];
    const float* cb1  = (const float*)d_in[12];
    const float* cW2  = (const float*)d_in[13];
    const float* cb2  = (const float*)d_in[14];
    const float* cgm  = (const float*)d_in[15];
    const float* cbt  = (const float*)d_in[16];
    const float* cmn  = (const float*)d_in[17];
    const float* cvr  = (const float*)d_in[18];
    const float* l1W  = (const float*)d_in[19];
    const float* l1b  = (const float*)d_in[20];
    const float* l2W  = (const float*)d_in[21];
    const float* l2b  = (const float*)d_in[22];
    float* out = (float*)d_out;

    int n = in_sizes[0] / 2;
    int e = in_sizes[1] / 2;
    int nl = in_sizes[11] / (HDIM * HDIM);
    int g = out_size;

    const int* src = ei;
    const int* dst = ei + e;

    __half *p_h, *p_hpre, *p_h1, *p_wprep;
    cudaGetSymbolAddress((void**)&p_h, g_h);
    cudaGetSymbolAddress((void**)&p_hpre, g_hpre);
    cudaGetSymbolAddress((void**)&p_h1, g_h1);
    cudaGetSymbolAddress((void**)&p_wprep, g_wprep);

    cudaFuncSetAttribute(gemm_mlp, cudaFuncAttributeMaxDynamicSharedMemorySize,
                         GEMM_SMEM_BYTES);

    int wtot = (1 + 2 * nl) * 16384;
    wprep_kernel<<<(wtot + 255) / 256, 256>>>(c1W2, cW1, cW2, nl, n);
    hist_kernel<<<(e + 255) / 256, 256>>>(dst, e, n);
    scan_kernel<<<1, 1024>>>(n);
    fill_kernel<<<(e + 255) / 256, 256>>>(src, dst, e, n);

    int gemm_blocks = (n + 127) / 128;
    int warp_grid = (n * 32 + 255) / 256;

    // Layer 0: agg(dim2)+MLP1 -> g_h1; single GEMM(W2)+BN -> g_h
    agg_mlp0_kernel<<<warp_grid, 256>>>(x, c1W1, c1b1, n);
    gemm_mlp<<<gemm_blocks, 256, GEMM_SMEM_BYTES>>>(
        p_h1, nullptr, p_wprep, nullptr, c1b2,
        c1gm, c1bt, c1mn, c1vr, p_h, n, 1.0f);

    // Layers 1..nl: agg (g_h -> g_hpre) -> fused MLP (W reuse) -> g_h
    for (int i = 0; i < nl; i++) {
        agg_kernel<<<warp_grid, 256>>>(n);
        gemm_mlp<<<gemm_blocks, 256, GEMM_SMEM_BYTES>>>(
            p_hpre,
            p_wprep + (size_t)(1 + i) * 32768,
            p_wprep + (size_t)(1 + nl + i) * 32768,
            cb1 + (size_t)i * HDIM, cb2 + (size_t)i * HDIM,
            cgm + (size_t)i * HDIM, cbt + (size_t)i * HDIM,
            cmn + (size_t)i * HDIM, cvr + (size_t)i * HDIM, p_h, n, A_SCALE);
    }

    // Fused pool + head
    pool_head_kernel<<<g, 128>>>(batch, n, l1W, l1b, l2W, l2b, out);
}